// round 14
// baseline (speedup 1.0000x reference)
#include <cuda_runtime.h>
#include <cfloat>
#include <math.h>
#include <stdint.h>

#define N_NODES 50000
#define N_PAIRS 4096
#define N_EDGES 500000
#define N_SCORE 1000000
#define FEAT 300
#define HID 128
#define HEADS 3
#define OUTC 10
#define SPLITK 3
#define SV_SZ (N_PAIRS * FEAT)
// split-K chunk: multiple of 4 so kBegin stays 16B-aligned for float4 loads
#define SV_CHUNK 1368

// ---------------- scratch (device globals; no runtime allocation) ----------------
__device__ float g_q[N_PAIRS * FEAT];
__device__ float g_k[N_PAIRS * FEAT];
__device__ float g_v[N_PAIRS * FEAT];
__device__ float g_S[(size_t)N_PAIRS * N_PAIRS];          // 64 MB
__device__ float g_attn[N_PAIRS * FEAT];
__device__ float g_fused[N_PAIRS * FEAT];
__device__ float g_part[(size_t)SPLITK * SV_SZ];          // split-K partials
__device__ float g_x[(size_t)N_NODES * FEAT];             // 60 MB
__device__ float g_h1[(size_t)N_NODES * HEADS * HID];     // 76.8 MB
__device__ float g_out1[(size_t)N_NODES * HEADS * HID];   // 76.8 MB
__device__ float g_es1[N_NODES * HEADS];
__device__ float g_ed1[N_NODES * HEADS];
__device__ float g_h2[N_NODES * OUTC];
__device__ float g_emb[N_NODES * OUTC];
__device__ float g_es2[N_NODES];
__device__ float g_ed2[N_NODES];
__device__ int   g_cnt[N_NODES];
__device__ int   g_off[N_NODES + 1];
__device__ int   g_cur[N_NODES];
__device__ int   g_csrc[N_EDGES];
__device__ int   g_win[N_NODES];

// ---------------- helpers ----------------
__device__ __forceinline__ float4 ld4k(const float* __restrict__ p, int k, int kEnd)
{
    if (k + 3 < kEnd) return *(const float4*)(p + k);
    float4 v = make_float4(0.f, 0.f, 0.f, 0.f);
    if (k + 0 < kEnd) v.x = p[k + 0];
    if (k + 1 < kEnd) v.y = p[k + 1];
    if (k + 2 < kEnd) v.z = p[k + 2];
    if (k + 3 < kEnd) v.w = p[k + 3];
    return v;
}

__device__ __forceinline__ uint32_t f2tf(float f)
{
    uint32_t u;
    asm("cvt.rna.tf32.f32 %0, %1;" : "=r"(u) : "f"(f));
    return u;
}

__device__ __forceinline__ void mma_tf32(float* c, const uint32_t* a, const uint32_t* b)
{
    asm volatile(
        "mma.sync.aligned.m16n8k8.row.col.f32.tf32.tf32.f32 "
        "{%0,%1,%2,%3}, {%4,%5,%6,%7}, {%8,%9}, {%0,%1,%2,%3};"
        : "+f"(c[0]), "+f"(c[1]), "+f"(c[2]), "+f"(c[3])
        : "r"(a[0]), "r"(a[1]), "r"(a[2]), "r"(a[3]),
          "r"(b[0]), "r"(b[1]));
}

// ---------------- tf32 tensor-core GEMM: 128x128x16 tile, 8 warps, m16n8k8 ----------------
// Double-buffered smem: one __syncthreads per k16 iteration; LDG latency hidden
// under the MMA block of the current stage.
// A: [M,K] row-major. B: [K,N] row-major (TB=false) or [N,K] row-major (TB=true).
// PARTIAL: raw partial result to C (alpha/bias/addm skipped).
// kBegin must be a multiple of 4.
template <bool TB, bool PARTIAL>
__device__ __forceinline__ void tf32_body(
    const float* __restrict__ A, const float* __restrict__ B,
    float* __restrict__ C, int M, int N, int K,
    int kBegin, int kEnd, float alpha,
    const float* __restrict__ bias, const float* __restrict__ addm, int ldc)
{
    constexpr int BM = 128, BN = 128, BK = 16, LDSM = 136;
    __shared__ uint32_t As[2][BK][LDSM];   // [buf][k][m], tf32 bits
    __shared__ uint32_t Bs[2][BK][LDSM];   // [buf][k][n], tf32 bits

    const int tid  = threadIdx.x;       // 256
    const int row0 = blockIdx.y * BM;
    const int col0 = blockIdx.x * BN;
    const int lane = tid & 31;
    const int wid  = tid >> 5;
    const int wm   = wid >> 2;          // 0..1 -> 64 rows each
    const int wn   = wid & 3;           // 0..3 -> 32 cols each
    const int lr   = lane >> 2;         // 0..7
    const int lc   = lane & 3;          // 0..3
    // loaders
    const int lrow = tid >> 1;          // 0..127
    const int lkq  = (tid & 1) * 4;     // 0 or 4
    const int bkk  = tid >> 5;          // 0..7
    const int bnq  = (tid & 31) * 4;    // 0..124

    float acc[4][4][4];
#pragma unroll
    for (int i = 0; i < 4; i++)
#pragma unroll
        for (int j = 0; j < 4; j++)
#pragma unroll
            for (int t = 0; t < 4; t++) acc[i][j][t] = 0.f;

    const int ga_row  = row0 + lrow;
    const int gb_colT = col0 + lrow;

    float4 pa[2], pb[2];

    auto fetch = [&](int k0) {
#pragma unroll
        for (int h = 0; h < 2; h++) {
            int kk = k0 + lkq + h * 8;
            pa[h] = (ga_row < M) ? ld4k(A + (size_t)ga_row * K, kk, kEnd)
                                 : make_float4(0.f, 0.f, 0.f, 0.f);
            if (TB) {
                pb[h] = (gb_colT < N) ? ld4k(B + (size_t)gb_colT * K, kk, kEnd)
                                      : make_float4(0.f, 0.f, 0.f, 0.f);
            } else {
                int gk = k0 + bkk + h * 8;
                pb[h] = make_float4(0.f, 0.f, 0.f, 0.f);
                if (gk < kEnd) {
                    const float* p = B + (size_t)gk * N;
                    int gc = col0 + bnq;
                    if (gc + 3 < N) pb[h] = *(const float4*)(p + gc);
                    else {
                        if (gc + 0 < N) pb[h].x = p[gc + 0];
                        if (gc + 1 < N) pb[h].y = p[gc + 1];
                        if (gc + 2 < N) pb[h].z = p[gc + 2];
                        if (gc + 3 < N) pb[h].w = p[gc + 3];
                    }
                }
            }
        }
    };

    auto commit = [&](int buf) {
#pragma unroll
        for (int h = 0; h < 2; h++) {
            As[buf][lkq + h * 8 + 0][lrow] = f2tf(pa[h].x);
            As[buf][lkq + h * 8 + 1][lrow] = f2tf(pa[h].y);
            As[buf][lkq + h * 8 + 2][lrow] = f2tf(pa[h].z);
            As[buf][lkq + h * 8 + 3][lrow] = f2tf(pa[h].w);
            if (TB) {
                Bs[buf][lkq + h * 8 + 0][lrow] = f2tf(pb[h].x);
                Bs[buf][lkq + h * 8 + 1][lrow] = f2tf(pb[h].y);
                Bs[buf][lkq + h * 8 + 2][lrow] = f2tf(pb[h].z);
                Bs[buf][lkq + h * 8 + 3][lrow] = f2tf(pb[h].w);
            } else {
                uint4 t;
                t.x = f2tf(pb[h].x); t.y = f2tf(pb[h].y);
                t.z = f2tf(pb[h].z); t.w = f2tf(pb[h].w);
                *(uint4*)&Bs[buf][bkk + h * 8][bnq] = t;
            }
        }
    };

    // prologue: stage 0
    fetch(kBegin);
    commit(0);
    __syncthreads();

    int cur = 0;
    for (int k0 = kBegin; k0 < kEnd; k0 += BK) {
        const bool has_next = (k0 + BK < kEnd);
        if (has_next) fetch(k0 + BK);     // LDGs in flight during compute

        // compute on current stage
#pragma unroll
        for (int s = 0; s < 2; s++) {
            const int k8 = s * 8;
            uint32_t af[4][4], bf[4][2];
#pragma unroll
            for (int mt = 0; mt < 4; mt++) {
                int m0 = wm * 64 + mt * 16;
                af[mt][0] = As[cur][k8 + lc][m0 + lr];
                af[mt][1] = As[cur][k8 + lc][m0 + lr + 8];
                af[mt][2] = As[cur][k8 + lc + 4][m0 + lr];
                af[mt][3] = As[cur][k8 + lc + 4][m0 + lr + 8];
            }
#pragma unroll
            for (int nt = 0; nt < 4; nt++) {
                int n0 = wn * 32 + nt * 8;
                bf[nt][0] = Bs[cur][k8 + lc][n0 + lr];
                bf[nt][1] = Bs[cur][k8 + lc + 4][n0 + lr];
            }
#pragma unroll
            for (int mt = 0; mt < 4; mt++)
#pragma unroll
                for (int nt = 0; nt < 4; nt++)
                    mma_tf32(acc[mt][nt], af[mt], bf[nt]);
        }

        if (has_next) {
            commit(cur ^ 1);
            __syncthreads();
        }
        cur ^= 1;
    }

    // epilogue
#pragma unroll
    for (int mt = 0; mt < 4; mt++) {
#pragma unroll
        for (int nt = 0; nt < 4; nt++) {
#pragma unroll
            for (int half = 0; half < 2; half++) {
                int r = row0 + wm * 64 + mt * 16 + lr + half * 8;
                int c = col0 + wn * 32 + nt * 8 + 2 * lc;
                if (r >= M) continue;
                float v0 = acc[mt][nt][half * 2 + 0];
                float v1 = acc[mt][nt][half * 2 + 1];
                if (!PARTIAL) {
                    v0 *= alpha; v1 *= alpha;
                    if (bias) { v0 += bias[c]; if (c + 1 < N) v1 += bias[c + 1]; }
                    if (addm) {
                        v0 += addm[(size_t)r * N + c];
                        if (c + 1 < N) v1 += addm[(size_t)r * N + c + 1];
                    }
                }
                float* dst = C + (size_t)r * ldc + c;
                if (c + 1 < N) *(float2*)dst = make_float2(v0, v1);
                else if (c < N) *dst = v0;
            }
        }
    }
}

template <bool TB>
__global__ void __launch_bounds__(256, 2) tgemm(
    const float* __restrict__ A, const float* __restrict__ B,
    float* __restrict__ C, int M, int N, int K, float alpha,
    const float* __restrict__ bias, const float* __restrict__ addm)
{
    tf32_body<TB, false>(A, B, C, M, N, K, 0, K, alpha, bias, addm, N);
}

// batched q/k/v projection: blockIdx.z selects (A, W, b, C)
__global__ void __launch_bounds__(256, 2) tgemm_qkv(
    const float* __restrict__ fsub, const float* __restrict__ fcom,
    const float* __restrict__ Wq, const float* __restrict__ bq,
    const float* __restrict__ Wk, const float* __restrict__ bk,
    const float* __restrict__ Wv, const float* __restrict__ bv)
{
    const float* A; const float* W; const float* b; float* C;
    if (blockIdx.z == 0)      { A = fsub; W = Wq; b = bq; C = g_q; }
    else if (blockIdx.z == 1) { A = fcom; W = Wk; b = bk; C = g_k; }
    else                      { A = fcom; W = Wv; b = bv; C = g_v; }
    tf32_body<false, false>(A, W, C, N_PAIRS, FEAT, FEAT, 0, FEAT, 1.f, b, nullptr, FEAT);
}

// split-K S@v partials: blockIdx.z = split id (kBegin multiple of 4 -> aligned)
__global__ void __launch_bounds__(256, 2) tgemm_sv_part()
{
    const int z = blockIdx.z;
    const int kb = z * SV_CHUNK;
    const int ke = min(N_PAIRS, kb + SV_CHUNK);
    tf32_body<false, true>(g_S, g_v, g_part + (size_t)z * SV_SZ,
                           N_PAIRS, FEAT, N_PAIRS, kb, ke, 1.f, nullptr, nullptr, FEAT);
}

__global__ void k_combine_sv(const float* __restrict__ fsub)
{
    int i = blockIdx.x * blockDim.x + threadIdx.x;
    if (i < SV_SZ)
        g_attn[i] = g_part[i] + g_part[i + SV_SZ] + g_part[i + 2 * SV_SZ] + fsub[i];
}

// ---------------- row softmax on g_S (4096 rows of 4096) ----------------
__global__ void k_softmax()
{
    int row = blockIdx.x;
    float* p = g_S + (size_t)row * N_PAIRS;
    int tid = threadIdx.x;               // 256
    float v[16];
    float mx = -FLT_MAX;
#pragma unroll
    for (int i = 0; i < 16; i++) { v[i] = p[tid + i * 256]; mx = fmaxf(mx, v[i]); }
    __shared__ float red[256];
    red[tid] = mx; __syncthreads();
    for (int s = 128; s > 0; s >>= 1) {
        if (tid < s) red[tid] = fmaxf(red[tid], red[tid + s]);
        __syncthreads();
    }
    mx = red[0]; __syncthreads();
    float sum = 0.f;
#pragma unroll
    for (int i = 0; i < 16; i++) { v[i] = expf(v[i] - mx); sum += v[i]; }
    red[tid] = sum; __syncthreads();
    for (int s = 128; s > 0; s >>= 1) {
        if (tid < s) red[tid] += red[tid + s];
        __syncthreads();
    }
    float inv = 1.f / red[0];
#pragma unroll
    for (int i = 0; i < 16; i++) p[tid + i * 256] = v[i] * inv;
}

// ---------------- CSR build ----------------
__global__ void k_reset()
{
    int i = blockIdx.x * blockDim.x + threadIdx.x;
    if (i < N_NODES) { g_cnt[i] = 0; g_win[i] = -1; }
}

__global__ void k_count(const int* __restrict__ dst)
{
    int e = blockIdx.x * blockDim.x + threadIdx.x;
    if (e < N_EDGES) atomicAdd(&g_cnt[dst[e]], 1);
}

__global__ void k_scan()
{
    __shared__ int sh[1024];
    __shared__ int carry;
    int tid = threadIdx.x;
    if (tid == 0) { carry = 0; g_off[0] = 0; }
    __syncthreads();
    for (int base = 0; base < N_NODES; base += 1024) {
        int i = base + tid;
        int v = (i < N_NODES) ? g_cnt[i] : 0;
        sh[tid] = v;
        __syncthreads();
        for (int o = 1; o < 1024; o <<= 1) {
            int t = (tid >= o) ? sh[tid - o] : 0;
            __syncthreads();
            sh[tid] += t;
            __syncthreads();
        }
        int c = carry;
        if (i < N_NODES) { g_off[i + 1] = c + sh[tid]; g_cur[i] = c + sh[tid] - v; }
        __syncthreads();
        if (tid == 0) carry += sh[1023];
        __syncthreads();
    }
}

__global__ void k_fill(const int* __restrict__ src, const int* __restrict__ dst)
{
    int e = blockIdx.x * blockDim.x + threadIdx.x;
    if (e < N_EDGES) {
        int d = dst[e];
        int pos = atomicAdd(&g_cur[d], 1);
        g_csrc[pos] = src[e];
    }
}

// ---------------- feature scatter (last index wins) ----------------
__global__ void k_copyx(const float* __restrict__ x)
{
    int i = blockIdx.x * blockDim.x + threadIdx.x;
    const int n4 = (N_NODES * FEAT) / 4;
    if (i < n4) ((float4*)g_x)[i] = ((const float4*)x)[i];
}

__global__ void k_winner(const int* __restrict__ com_idx)
{
    int i = blockIdx.x * blockDim.x + threadIdx.x;
    if (i < N_PAIRS) atomicMax(&g_win[com_idx[i]], i);
}

__global__ void k_scatter(const int* __restrict__ com_idx)
{
    int i = blockIdx.x;
    int node = com_idx[i];
    if (g_win[node] != i) return;
    for (int c = threadIdx.x; c < FEAT; c += blockDim.x)
        g_x[(size_t)node * FEAT + c] = g_fused[(size_t)i * FEAT + c];
}

// ---------------- GAT layer 1: per-node attention coefficients ----------------
__global__ void k_e1(const float* __restrict__ a_src1, const float* __restrict__ a_dst1)
{
    int gw = (blockIdx.x * blockDim.x + threadIdx.x) >> 5;
    int lane = threadIdx.x & 31;
    if (gw >= N_NODES) return;
    const float* hp = g_h1 + (size_t)gw * (HEADS * HID);
#pragma unroll
    for (int h = 0; h < HEADS; h++) {
        float ps = 0.f, pd = 0.f;
#pragma unroll
        for (int t = 0; t < 4; t++) {
            int c = h * HID + lane + t * 32;
            float hv = hp[c];
            ps += hv * a_src1[c];
            pd += hv * a_dst1[c];
        }
        for (int o = 16; o; o >>= 1) {
            ps += __shfl_xor_sync(0xffffffffu, ps, o);
            pd += __shfl_xor_sync(0xffffffffu, pd, o);
        }
        if (lane == 0) { g_es1[gw * 3 + h] = ps; g_ed1[gw * 3 + h] = pd; }
    }
}

__device__ __forceinline__ float lrelu(float x) { return x > 0.f ? x : 0.2f * x; }

// ---------------- GAT layer 1: softmax-aggregate per dst node, fused ELU ----------------
__global__ void k_agg1(const float* __restrict__ b1)
{
    __shared__ float shred[3][128];
    __shared__ float shal[64][3];
    __shared__ int   shsrc[64];
    const int n = blockIdx.x;
    const int tid = threadIdx.x;          // 128
    const int beg = g_off[n];
    const int deg = g_off[n + 1] - beg;
    const int tot = deg + 1;              // + self loop
    float edn[3];
#pragma unroll
    for (int h = 0; h < 3; h++) edn[h] = g_ed1[n * 3 + h];

    float mx[3] = { -FLT_MAX, -FLT_MAX, -FLT_MAX };
    for (int t = tid; t < tot; t += 128) {
        int s = (t < deg) ? g_csrc[beg + t] : n;
#pragma unroll
        for (int h = 0; h < 3; h++) {
            float e = lrelu(g_es1[s * 3 + h] + edn[h]);
            mx[h] = fmaxf(mx[h], e);
        }
    }
#pragma unroll
    for (int h = 0; h < 3; h++) shred[h][tid] = mx[h];
    __syncthreads();
    for (int s = 64; s > 0; s >>= 1) {
        if (tid < s) {
#pragma unroll
            for (int h = 0; h < 3; h++)
                shred[h][tid] = fmaxf(shred[h][tid], shred[h][tid + s]);
        }
        __syncthreads();
    }
#pragma unroll
    for (int h = 0; h < 3; h++) mx[h] = shred[h][0];
    __syncthreads();

    float sm[3] = { 0.f, 0.f, 0.f };
    for (int t = tid; t < tot; t += 128) {
        int s = (t < deg) ? g_csrc[beg + t] : n;
#pragma unroll
        for (int h = 0; h < 3; h++) {
            float e = lrelu(g_es1[s * 3 + h] + edn[h]);
            sm[h] += expf(e - mx[h]);
        }
    }
#pragma unroll
    for (int h = 0; h < 3; h++) shred[h][tid] = sm[h];
    __syncthreads();
    for (int s = 64; s > 0; s >>= 1) {
        if (tid < s) {
#pragma unroll
            for (int h = 0; h < 3; h++)
                shred[h][tid] += shred[h][tid + s];
        }
        __syncthreads();
    }
    float inv[3];
#pragma unroll
    for (int h = 0; h < 3; h++) inv[h] = 1.f / (shred[h][0] + 1e-16f);
    __syncthreads();

    float acc[3] = { 0.f, 0.f, 0.f };
    for (int base = 0; base < tot; base += 64) {
        int nn = min(64, tot - base);
        if (tid < nn) {
            int t = base + tid;
            int s = (t < deg) ? g_csrc[beg + t] : n;
            shsrc[tid] = s;
#pragma unroll
            for (int h = 0; h < 3; h++) {
                float e = lrelu(g_es1[s * 3 + h] + edn[h]);
                shal[tid][h] = expf(e - mx[h]) * inv[h];
            }
        }
        __syncthreads();
        for (int j = 0; j < nn; j++) {
            const float* hp = g_h1 + (size_t)shsrc[j] * (HEADS * HID);
            float a0 = shal[j][0], a1 = shal[j][1], a2 = shal[j][2];
            acc[0] += hp[tid] * a0;
            acc[1] += hp[128 + tid] * a1;
            acc[2] += hp[256 + tid] * a2;
        }
        __syncthreads();
    }
#pragma unroll
    for (int h = 0; h < 3; h++) {
        float v = acc[h] + b1[h * HID + tid];
        g_out1[(size_t)n * (HEADS * HID) + h * HID + tid] = v > 0.f ? v : expm1f(v);
    }
}

// ---------------- GAT layer 2: h2 = out1 @ W2 (warp per row, N=10) ----------------
__global__ void k_h2(const float* __restrict__ W2)
{
    int gw = (blockIdx.x * blockDim.x + threadIdx.x) >> 5;
    int lane = threadIdx.x & 31;
    if (gw >= N_NODES) return;
    const float* a = g_out1 + (size_t)gw * (HEADS * HID);
    float acc[OUTC];
#pragma unroll
    for (int j = 0; j < OUTC; j++) acc[j] = 0.f;
    for (int k = lane; k < HEADS * HID; k += 32) {
        float av = a[k];
#pragma unroll
        for (int j = 0; j < OUTC; j++) acc[j] += av * W2[k * OUTC + j];
    }
#pragma unroll
    for (int j = 0; j < OUTC; j++)
        for (int o = 16; o; o >>= 1)
            acc[j] += __shfl_xor_sync(0xffffffffu, acc[j], o);
    if (lane == 0) {
#pragma unroll
        for (int j = 0; j < OUTC; j++) g_h2[gw * OUTC + j] = acc[j];
    }
}

__global__ void k_e2(const float* __restrict__ a_src2, const float* __restrict__ a_dst2)
{
    int n = blockIdx.x * blockDim.x + threadIdx.x;
    if (n >= N_NODES) return;
    float s = 0.f, d = 0.f;
#pragma unroll
    for (int j = 0; j < OUTC; j++) {
        float h = g_h2[n * OUTC + j];
        s += h * a_src2[j];
        d += h * a_dst2[j];
    }
    g_es2[n] = s; g_ed2[n] = d;
}

// ---------------- GAT layer 2 aggregate (warp per node) ----------------
__global__ void k_agg2(const float* __restrict__ b2)
{
    int gw = (blockIdx.x * blockDim.x + threadIdx.x) >> 5;
    int lane = threadIdx.x & 31;
    if (gw >= N_NODES) return;
    const int n = gw;
    const int beg = g_off[n];
    const int deg = g_off[n + 1] - beg;
    const int tot = deg + 1;
    float edn = g_ed2[n];
    float mx = -FLT_MAX;
    for (int t = lane; t < tot; t += 32) {
        int s = (t < deg) ? g_csrc[beg + t] : n;
        mx = fmaxf(mx, lrelu(g_es2[s] + edn));
    }
    for (int o = 16; o; o >>= 1) mx = fmaxf(mx, __shfl_xor_sync(0xffffffffu, mx, o));
    float sm = 0.f;
    for (int t = lane; t < tot; t += 32) {
        int s = (t < deg) ? g_csrc[beg + t] : n;
        sm += expf(lrelu(g_es2[s] + edn) - mx);
    }
    for (int o = 16; o; o >>= 1) sm += __shfl_xor_sync(0xffffffffu, sm, o);
    float inv = 1.f / (sm + 1e-16f);
    float acc = 0.f;
    for (int base = 0; base < tot; base += 32) {
        int t = base + lane;
        float al = 0.f; int ms = n;
        if (t < tot) {
            int s = (t < deg) ? g_csrc[beg + t] : n;
            ms = s;
            al = expf(lrelu(g_es2[s] + edn) - mx) * inv;
        }
        int nn = min(32, tot - base);
        for (int j = 0; j < nn; j++) {
            float a = __shfl_sync(0xffffffffu, al, j);
            int s = __shfl_sync(0xffffffffu, ms, j);
            if (lane < OUTC) acc += g_h2[s * OUTC + lane] * a;
        }
    }
    if (lane < OUTC) g_emb[n * OUTC + lane] = acc + b2[lane];
}

// ---------------- pair scoring ----------------
__global__ void k_score(const int* __restrict__ pair, float* __restrict__ out)
{
    int p = blockIdx.x * blockDim.x + threadIdx.x;
    if (p >= N_SCORE) return;
    int i = pair[2 * p], j = pair[2 * p + 1];
    const float* a = g_emb + (size_t)i * OUTC;
    const float* b = g_emb + (size_t)j * OUTC;
    float s = 0.f;
#pragma unroll
    for (int c = 0; c < OUTC; c++) s += a[c] * b[c];
    out[p] = s;
}

// ---------------- host ----------------
static inline dim3 gemm_grid(int M, int N, int z = 1)
{ return dim3((N + 127) / 128, (M + 127) / 128, z); }

extern "C" void kernel_launch(void* const* d_in, const int* in_sizes, int n_in,
                              void* d_out, int out_size)
{
    const float* feature_sub = (const float*)d_in[0];
    const float* feature_com = (const float*)d_in[1];
    const float* x           = (const float*)d_in[2];
    const int*   com_idx     = (const int*)d_in[3];
    const int*   edge_index  = (const int*)d_in[4];
    const int*   pair_idx    = (const int*)d_in[5];
    const float* Wq = (const float*)d_in[6];   const float* bq = (const float*)d_in[7];
    const float* Wk = (const float*)d_in[8];   const float* bk = (const float*)d_in[9];
    const float* Wv = (const float*)d_in[10];  const float* bv = (const float*)d_in[11];
    const float* Wf = (const float*)d_in[12];  const float* bf = (const float*)d_in[13];
    const float* W1 = (const float*)d_in[14];
    const float* a_src1 = (const float*)d_in[15];
    const float* a_dst1 = (const float*)d_in[16];
    const float* b1 = (const float*)d_in[17];
    const float* W2 = (const float*)d_in[18];
    const float* a_src2 = (const float*)d_in[19];
    const float* a_dst2 = (const float*)d_in[20];
    const float* b2 = (const float*)d_in[21];
    float* out = (float*)d_out;

    const int* esrc = edge_index;
    const int* edst = edge_index + N_EDGES;

    float *pq, *pk, *pS, *pattn, *pfused, *px, *ph1;
    cudaGetSymbolAddress((void**)&pq,    g_q);
    cudaGetSymbolAddress((void**)&pk,    g_k);
    cudaGetSymbolAddress((void**)&pS,    g_S);
    cudaGetSymbolAddress((void**)&pattn, g_attn);
    cudaGetSymbolAddress((void**)&pfused,g_fused);
    cudaGetSymbolAddress((void**)&px,    g_x);
    cudaGetSymbolAddress((void**)&ph1,   g_h1);

    // --- CSR build ---
    k_reset<<<(N_NODES + 255) / 256, 256>>>();
    k_count<<<(N_EDGES + 255) / 256, 256>>>(edst);
    k_scan<<<1, 1024>>>();
    k_fill<<<(N_EDGES + 255) / 256, 256>>>(esrc, edst);

    // --- cross-attention (tf32 tensor cores) ---
    tgemm_qkv<<<gemm_grid(N_PAIRS, FEAT, 3), 256>>>(
        feature_sub, feature_com, Wq, bq, Wk, bk, Wv, bv);
    tgemm<true><<<gemm_grid(N_PAIRS, N_PAIRS), 256>>>(
        pq, pk, pS, N_PAIRS, N_PAIRS, FEAT, 1.f / sqrtf((float)FEAT), nullptr, nullptr);
    k_softmax<<<N_PAIRS, 256>>>();
    tgemm_sv_part<<<gemm_grid(N_PAIRS, FEAT, SPLITK), 256>>>();
    k_combine_sv<<<(SV_SZ + 255) / 256, 256>>>(feature_sub);
    tgemm<false><<<gemm_grid(N_PAIRS, FEAT), 256>>>(
        pattn, Wf, pfused, N_PAIRS, FEAT, FEAT, 1.f, bf, nullptr);

    // --- write fused features into node feature copy (last-index-wins) ---
    k_copyx<<<((N_NODES * FEAT / 4) + 255) / 256, 256>>>(x);
    k_winner<<<(N_PAIRS + 255) / 256, 256>>>(com_idx);
    k_scatter<<<N_PAIRS, 128>>>(com_idx);

    // --- GAT layer 1 ---
    tgemm<false><<<gemm_grid(N_NODES, HEADS * HID), 256>>>(
        px, W1, ph1, N_NODES, HEADS * HID, FEAT, 1.f, nullptr, nullptr);
    k_e1<<<(N_NODES * 32 + 255) / 256, 256>>>(a_src1, a_dst1);
    k_agg1<<<N_NODES, 128>>>(b1);

    // --- GAT layer 2 ---
    k_h2<<<(N_NODES * 32 + 255) / 256, 256>>>(W2);
    k_e2<<<(N_NODES + 255) / 256, 256>>>(a_src2, a_dst2);
    k_agg2<<<(N_NODES * 32 + 255) / 256, 256>>>(b2);

    // --- pair scores ---
    k_score<<<(N_SCORE + 255) / 256, 256>>>(pair_idx, out);
}

// round 15
// speedup vs baseline: 1.0021x; 1.0021x over previous
#include <cuda_runtime.h>
#include <cfloat>
#include <math.h>
#include <stdint.h>

#define N_NODES 50000
#define N_PAIRS 4096
#define N_EDGES 500000
#define N_SCORE 1000000
#define FEAT 300
#define HID 128
#define HEADS 3
#define OUTC 10
#define SPLITK 3
#define SV_SZ (N_PAIRS * FEAT)
// split-K chunk: multiple of 4 so kBegin stays 16B-aligned for float4 loads
#define SV_CHUNK 1368

// ---------------- scratch (device globals; no runtime allocation) ----------------
__device__ float g_q[N_PAIRS * FEAT];
__device__ float g_k[N_PAIRS * FEAT];
__device__ float g_v[N_PAIRS * FEAT];
__device__ float g_S[(size_t)N_PAIRS * N_PAIRS];          // 64 MB
__device__ float g_attn[N_PAIRS * FEAT];
__device__ float g_fused[N_PAIRS * FEAT];
__device__ float g_part[(size_t)SPLITK * SV_SZ];          // split-K partials
__device__ float g_x[(size_t)N_NODES * FEAT];             // 60 MB
__device__ float g_h1[(size_t)N_NODES * HEADS * HID];     // 76.8 MB
__device__ float g_out1[(size_t)N_NODES * HEADS * HID];   // 76.8 MB
__device__ float g_es1[N_NODES * HEADS];
__device__ float g_ed1[N_NODES * HEADS];
__device__ float g_h2[N_NODES * OUTC];
__device__ float g_emb[N_NODES * OUTC];
__device__ float g_es2[N_NODES];
__device__ float g_ed2[N_NODES];
__device__ int   g_cnt[N_NODES];
__device__ int   g_off[N_NODES + 1];
__device__ int   g_cur[N_NODES];
__device__ int   g_csrc[N_EDGES];
__device__ int   g_win[N_NODES];

// ---------------- helpers ----------------
__device__ __forceinline__ float4 ld4k(const float* __restrict__ p, int k, int kEnd)
{
    if (k + 3 < kEnd) return *(const float4*)(p + k);
    float4 v = make_float4(0.f, 0.f, 0.f, 0.f);
    if (k + 0 < kEnd) v.x = p[k + 0];
    if (k + 1 < kEnd) v.y = p[k + 1];
    if (k + 2 < kEnd) v.z = p[k + 2];
    if (k + 3 < kEnd) v.w = p[k + 3];
    return v;
}

__device__ __forceinline__ uint32_t f2tf(float f)
{
    uint32_t u;
    asm("cvt.rna.tf32.f32 %0, %1;" : "=r"(u) : "f"(f));
    return u;
}

__device__ __forceinline__ void mma_tf32(float* c, const uint32_t* a, const uint32_t* b)
{
    asm volatile(
        "mma.sync.aligned.m16n8k8.row.col.f32.tf32.tf32.f32 "
        "{%0,%1,%2,%3}, {%4,%5,%6,%7}, {%8,%9}, {%0,%1,%2,%3};"
        : "+f"(c[0]), "+f"(c[1]), "+f"(c[2]), "+f"(c[3])
        : "r"(a[0]), "r"(a[1]), "r"(a[2]), "r"(a[3]),
          "r"(b[0]), "r"(b[1]));
}

// ---------------- tf32 tensor-core GEMM: 128x128x16 tile, 8 warps, m16n8k8 ----------------
// Double-buffered smem: one __syncthreads per k16 iteration; LDG latency hidden
// under the MMA block of the current stage.
// A: [M,K] row-major. B: [K,N] row-major (TB=false) or [N,K] row-major (TB=true).
// PARTIAL: raw partial result to C (alpha/bias/addm skipped).
// kBegin must be a multiple of 4.
template <bool TB, bool PARTIAL>
__device__ __forceinline__ void tf32_body(
    const float* __restrict__ A, const float* __restrict__ B,
    float* __restrict__ C, int M, int N, int K,
    int kBegin, int kEnd, float alpha,
    const float* __restrict__ bias, const float* __restrict__ addm, int ldc)
{
    constexpr int BM = 128, BN = 128, BK = 16, LDSM = 136;
    __shared__ uint32_t As[2][BK][LDSM];   // [buf][k][m], tf32 bits
    __shared__ uint32_t Bs[2][BK][LDSM];   // [buf][k][n], tf32 bits

    const int tid  = threadIdx.x;       // 256
    const int row0 = blockIdx.y * BM;
    const int col0 = blockIdx.x * BN;
    const int lane = tid & 31;
    const int wid  = tid >> 5;
    const int wm   = wid >> 2;          // 0..1 -> 64 rows each
    const int wn   = wid & 3;           // 0..3 -> 32 cols each
    const int lr   = lane >> 2;         // 0..7
    const int lc   = lane & 3;          // 0..3
    // loaders
    const int lrow = tid >> 1;          // 0..127
    const int lkq  = (tid & 1) * 4;     // 0 or 4
    const int bkk  = tid >> 5;          // 0..7
    const int bnq  = (tid & 31) * 4;    // 0..124

    float acc[4][4][4];
#pragma unroll
    for (int i = 0; i < 4; i++)
#pragma unroll
        for (int j = 0; j < 4; j++)
#pragma unroll
            for (int t = 0; t < 4; t++) acc[i][j][t] = 0.f;

    const int ga_row  = row0 + lrow;
    const int gb_colT = col0 + lrow;

    float4 pa[2], pb[2];

    auto fetch = [&](int k0) {
#pragma unroll
        for (int h = 0; h < 2; h++) {
            int kk = k0 + lkq + h * 8;
            pa[h] = (ga_row < M) ? ld4k(A + (size_t)ga_row * K, kk, kEnd)
                                 : make_float4(0.f, 0.f, 0.f, 0.f);
            if (TB) {
                pb[h] = (gb_colT < N) ? ld4k(B + (size_t)gb_colT * K, kk, kEnd)
                                      : make_float4(0.f, 0.f, 0.f, 0.f);
            } else {
                int gk = k0 + bkk + h * 8;
                pb[h] = make_float4(0.f, 0.f, 0.f, 0.f);
                if (gk < kEnd) {
                    const float* p = B + (size_t)gk * N;
                    int gc = col0 + bnq;
                    if (gc + 3 < N) pb[h] = *(const float4*)(p + gc);
                    else {
                        if (gc + 0 < N) pb[h].x = p[gc + 0];
                        if (gc + 1 < N) pb[h].y = p[gc + 1];
                        if (gc + 2 < N) pb[h].z = p[gc + 2];
                        if (gc + 3 < N) pb[h].w = p[gc + 3];
                    }
                }
            }
        }
    };

    auto commit = [&](int buf) {
#pragma unroll
        for (int h = 0; h < 2; h++) {
            As[buf][lkq + h * 8 + 0][lrow] = f2tf(pa[h].x);
            As[buf][lkq + h * 8 + 1][lrow] = f2tf(pa[h].y);
            As[buf][lkq + h * 8 + 2][lrow] = f2tf(pa[h].z);
            As[buf][lkq + h * 8 + 3][lrow] = f2tf(pa[h].w);
            if (TB) {
                Bs[buf][lkq + h * 8 + 0][lrow] = f2tf(pb[h].x);
                Bs[buf][lkq + h * 8 + 1][lrow] = f2tf(pb[h].y);
                Bs[buf][lkq + h * 8 + 2][lrow] = f2tf(pb[h].z);
                Bs[buf][lkq + h * 8 + 3][lrow] = f2tf(pb[h].w);
            } else {
                uint4 t;
                t.x = f2tf(pb[h].x); t.y = f2tf(pb[h].y);
                t.z = f2tf(pb[h].z); t.w = f2tf(pb[h].w);
                *(uint4*)&Bs[buf][bkk + h * 8][bnq] = t;
            }
        }
    };

    // prologue: stage 0
    fetch(kBegin);
    commit(0);
    __syncthreads();

    int cur = 0;
    for (int k0 = kBegin; k0 < kEnd; k0 += BK) {
        const bool has_next = (k0 + BK < kEnd);
        if (has_next) fetch(k0 + BK);     // LDGs in flight during compute

        // compute on current stage
#pragma unroll
        for (int s = 0; s < 2; s++) {
            const int k8 = s * 8;
            uint32_t af[4][4], bf[4][2];
#pragma unroll
            for (int mt = 0; mt < 4; mt++) {
                int m0 = wm * 64 + mt * 16;
                af[mt][0] = As[cur][k8 + lc][m0 + lr];
                af[mt][1] = As[cur][k8 + lc][m0 + lr + 8];
                af[mt][2] = As[cur][k8 + lc + 4][m0 + lr];
                af[mt][3] = As[cur][k8 + lc + 4][m0 + lr + 8];
            }
#pragma unroll
            for (int nt = 0; nt < 4; nt++) {
                int n0 = wn * 32 + nt * 8;
                bf[nt][0] = Bs[cur][k8 + lc][n0 + lr];
                bf[nt][1] = Bs[cur][k8 + lc + 4][n0 + lr];
            }
#pragma unroll
            for (int mt = 0; mt < 4; mt++)
#pragma unroll
                for (int nt = 0; nt < 4; nt++)
                    mma_tf32(acc[mt][nt], af[mt], bf[nt]);
        }

        if (has_next) {
            commit(cur ^ 1);
            __syncthreads();
        }
        cur ^= 1;
    }

    // epilogue
#pragma unroll
    for (int mt = 0; mt < 4; mt++) {
#pragma unroll
        for (int nt = 0; nt < 4; nt++) {
#pragma unroll
            for (int half = 0; half < 2; half++) {
                int r = row0 + wm * 64 + mt * 16 + lr + half * 8;
                int c = col0 + wn * 32 + nt * 8 + 2 * lc;
                if (r >= M) continue;
                float v0 = acc[mt][nt][half * 2 + 0];
                float v1 = acc[mt][nt][half * 2 + 1];
                if (!PARTIAL) {
                    v0 *= alpha; v1 *= alpha;
                    if (bias) { v0 += bias[c]; if (c + 1 < N) v1 += bias[c + 1]; }
                    if (addm) {
                        v0 += addm[(size_t)r * N + c];
                        if (c + 1 < N) v1 += addm[(size_t)r * N + c + 1];
                    }
                }
                float* dst = C + (size_t)r * ldc + c;
                if (c + 1 < N) *(float2*)dst = make_float2(v0, v1);
                else if (c < N) *dst = v0;
            }
        }
    }
}

template <bool TB>
__global__ void __launch_bounds__(256, 2) tgemm(
    const float* __restrict__ A, const float* __restrict__ B,
    float* __restrict__ C, int M, int N, int K, float alpha,
    const float* __restrict__ bias, const float* __restrict__ addm)
{
    tf32_body<TB, false>(A, B, C, M, N, K, 0, K, alpha, bias, addm, N);
}

// batched q/k/v projection: blockIdx.z selects (A, W, b, C)
__global__ void __launch_bounds__(256, 2) tgemm_qkv(
    const float* __restrict__ fsub, const float* __restrict__ fcom,
    const float* __restrict__ Wq, const float* __restrict__ bq,
    const float* __restrict__ Wk, const float* __restrict__ bk,
    const float* __restrict__ Wv, const float* __restrict__ bv)
{
    const float* A; const float* W; const float* b; float* C;
    if (blockIdx.z == 0)      { A = fsub; W = Wq; b = bq; C = g_q; }
    else if (blockIdx.z == 1) { A = fcom; W = Wk; b = bk; C = g_k; }
    else                      { A = fcom; W = Wv; b = bv; C = g_v; }
    tf32_body<false, false>(A, W, C, N_PAIRS, FEAT, FEAT, 0, FEAT, 1.f, b, nullptr, FEAT);
}

// split-K S@v partials: blockIdx.z = split id (kBegin multiple of 4 -> aligned)
__global__ void __launch_bounds__(256, 2) tgemm_sv_part()
{
    const int z = blockIdx.z;
    const int kb = z * SV_CHUNK;
    const int ke = min(N_PAIRS, kb + SV_CHUNK);
    tf32_body<false, true>(g_S, g_v, g_part + (size_t)z * SV_SZ,
                           N_PAIRS, FEAT, N_PAIRS, kb, ke, 1.f, nullptr, nullptr, FEAT);
}

__global__ void k_combine_sv(const float* __restrict__ fsub)
{
    int i = blockIdx.x * blockDim.x + threadIdx.x;
    if (i < SV_SZ)
        g_attn[i] = g_part[i] + g_part[i + SV_SZ] + g_part[i + 2 * SV_SZ] + fsub[i];
}

// ---------------- row softmax on g_S (4096 rows of 4096) ----------------
__global__ void k_softmax()
{
    int row = blockIdx.x;
    float* p = g_S + (size_t)row * N_PAIRS;
    int tid = threadIdx.x;               // 256
    float v[16];
    float mx = -FLT_MAX;
#pragma unroll
    for (int i = 0; i < 16; i++) { v[i] = p[tid + i * 256]; mx = fmaxf(mx, v[i]); }
    __shared__ float red[256];
    red[tid] = mx; __syncthreads();
    for (int s = 128; s > 0; s >>= 1) {
        if (tid < s) red[tid] = fmaxf(red[tid], red[tid + s]);
        __syncthreads();
    }
    mx = red[0]; __syncthreads();
    float sum = 0.f;
#pragma unroll
    for (int i = 0; i < 16; i++) { v[i] = expf(v[i] - mx); sum += v[i]; }
    red[tid] = sum; __syncthreads();
    for (int s = 128; s > 0; s >>= 1) {
        if (tid < s) red[tid] += red[tid + s];
        __syncthreads();
    }
    float inv = 1.f / red[0];
#pragma unroll
    for (int i = 0; i < 16; i++) p[tid + i * 256] = v[i] * inv;
}

// ---------------- CSR build ----------------
__global__ void k_reset()
{
    int i = blockIdx.x * blockDim.x + threadIdx.x;
    if (i < N_NODES) { g_cnt[i] = 0; g_win[i] = -1; }
}

__global__ void k_count(const int* __restrict__ dst)
{
    int e = blockIdx.x * blockDim.x + threadIdx.x;
    if (e < N_EDGES) atomicAdd(&g_cnt[dst[e]], 1);
}

__global__ void k_scan()
{
    __shared__ int sh[1024];
    __shared__ int carry;
    int tid = threadIdx.x;
    if (tid == 0) { carry = 0; g_off[0] = 0; }
    __syncthreads();
    for (int base = 0; base < N_NODES; base += 1024) {
        int i = base + tid;
        int v = (i < N_NODES) ? g_cnt[i] : 0;
        sh[tid] = v;
        __syncthreads();
        for (int o = 1; o < 1024; o <<= 1) {
            int t = (tid >= o) ? sh[tid - o] : 0;
            __syncthreads();
            sh[tid] += t;
            __syncthreads();
        }
        int c = carry;
        if (i < N_NODES) { g_off[i + 1] = c + sh[tid]; g_cur[i] = c + sh[tid] - v; }
        __syncthreads();
        if (tid == 0) carry += sh[1023];
        __syncthreads();
    }
}

__global__ void k_fill(const int* __restrict__ src, const int* __restrict__ dst)
{
    int e = blockIdx.x * blockDim.x + threadIdx.x;
    if (e < N_EDGES) {
        int d = dst[e];
        int pos = atomicAdd(&g_cur[d], 1);
        g_csrc[pos] = src[e];
    }
}

// ---------------- feature scatter (last index wins) ----------------
__global__ void k_copyx(const float* __restrict__ x)
{
    int i = blockIdx.x * blockDim.x + threadIdx.x;
    const int n4 = (N_NODES * FEAT) / 4;
    if (i < n4) ((float4*)g_x)[i] = ((const float4*)x)[i];
}

__global__ void k_winner(const int* __restrict__ com_idx)
{
    int i = blockIdx.x * blockDim.x + threadIdx.x;
    if (i < N_PAIRS) atomicMax(&g_win[com_idx[i]], i);
}

__global__ void k_scatter(const int* __restrict__ com_idx)
{
    int i = blockIdx.x;
    int node = com_idx[i];
    if (g_win[node] != i) return;
    for (int c = threadIdx.x; c < FEAT; c += blockDim.x)
        g_x[(size_t)node * FEAT + c] = g_fused[(size_t)i * FEAT + c];
}

// ---------------- GAT layer 1: per-node attention coefficients ----------------
__global__ void k_e1(const float* __restrict__ a_src1, const float* __restrict__ a_dst1)
{
    int gw = (blockIdx.x * blockDim.x + threadIdx.x) >> 5;
    int lane = threadIdx.x & 31;
    if (gw >= N_NODES) return;
    const float* hp = g_h1 + (size_t)gw * (HEADS * HID);
#pragma unroll
    for (int h = 0; h < HEADS; h++) {
        float ps = 0.f, pd = 0.f;
#pragma unroll
        for (int t = 0; t < 4; t++) {
            int c = h * HID + lane + t * 32;
            float hv = hp[c];
            ps += hv * a_src1[c];
            pd += hv * a_dst1[c];
        }
        for (int o = 16; o; o >>= 1) {
            ps += __shfl_xor_sync(0xffffffffu, ps, o);
            pd += __shfl_xor_sync(0xffffffffu, pd, o);
        }
        if (lane == 0) { g_es1[gw * 3 + h] = ps; g_ed1[gw * 3 + h] = pd; }
    }
}

__device__ __forceinline__ float lrelu(float x) { return x > 0.f ? x : 0.2f * x; }

// ---------------- GAT layer 1: softmax-aggregate per dst node, fused ELU ----------------
__global__ void k_agg1(const float* __restrict__ b1)
{
    __shared__ float shred[3][128];
    __shared__ float shal[64][3];
    __shared__ int   shsrc[64];
    const int n = blockIdx.x;
    const int tid = threadIdx.x;          // 128
    const int beg = g_off[n];
    const int deg = g_off[n + 1] - beg;
    const int tot = deg + 1;              // + self loop
    float edn[3];
#pragma unroll
    for (int h = 0; h < 3; h++) edn[h] = g_ed1[n * 3 + h];

    float mx[3] = { -FLT_MAX, -FLT_MAX, -FLT_MAX };
    for (int t = tid; t < tot; t += 128) {
        int s = (t < deg) ? g_csrc[beg + t] : n;
#pragma unroll
        for (int h = 0; h < 3; h++) {
            float e = lrelu(g_es1[s * 3 + h] + edn[h]);
            mx[h] = fmaxf(mx[h], e);
        }
    }
#pragma unroll
    for (int h = 0; h < 3; h++) shred[h][tid] = mx[h];
    __syncthreads();
    for (int s = 64; s > 0; s >>= 1) {
        if (tid < s) {
#pragma unroll
            for (int h = 0; h < 3; h++)
                shred[h][tid] = fmaxf(shred[h][tid], shred[h][tid + s]);
        }
        __syncthreads();
    }
#pragma unroll
    for (int h = 0; h < 3; h++) mx[h] = shred[h][0];
    __syncthreads();

    float sm[3] = { 0.f, 0.f, 0.f };
    for (int t = tid; t < tot; t += 128) {
        int s = (t < deg) ? g_csrc[beg + t] : n;
#pragma unroll
        for (int h = 0; h < 3; h++) {
            float e = lrelu(g_es1[s * 3 + h] + edn[h]);
            sm[h] += expf(e - mx[h]);
        }
    }
#pragma unroll
    for (int h = 0; h < 3; h++) shred[h][tid] = sm[h];
    __syncthreads();
    for (int s = 64; s > 0; s >>= 1) {
        if (tid < s) {
#pragma unroll
            for (int h = 0; h < 3; h++)
                shred[h][tid] += shred[h][tid + s];
        }
        __syncthreads();
    }
    float inv[3];
#pragma unroll
    for (int h = 0; h < 3; h++) inv[h] = 1.f / (shred[h][0] + 1e-16f);
    __syncthreads();

    float acc[3] = { 0.f, 0.f, 0.f };
    for (int base = 0; base < tot; base += 64) {
        int nn = min(64, tot - base);
        if (tid < nn) {
            int t = base + tid;
            int s = (t < deg) ? g_csrc[beg + t] : n;
            shsrc[tid] = s;
#pragma unroll
            for (int h = 0; h < 3; h++) {
                float e = lrelu(g_es1[s * 3 + h] + edn[h]);
                shal[tid][h] = expf(e - mx[h]) * inv[h];
            }
        }
        __syncthreads();
        for (int j = 0; j < nn; j++) {
            const float* hp = g_h1 + (size_t)shsrc[j] * (HEADS * HID);
            float a0 = shal[j][0], a1 = shal[j][1], a2 = shal[j][2];
            acc[0] += hp[tid] * a0;
            acc[1] += hp[128 + tid] * a1;
            acc[2] += hp[256 + tid] * a2;
        }
        __syncthreads();
    }
#pragma unroll
    for (int h = 0; h < 3; h++) {
        float v = acc[h] + b1[h * HID + tid];
        g_out1[(size_t)n * (HEADS * HID) + h * HID + tid] = v > 0.f ? v : expm1f(v);
    }
}

// ---------------- GAT layer 2: h2 = out1 @ W2 (warp per row, N=10) ----------------
__global__ void k_h2(const float* __restrict__ W2)
{
    int gw = (blockIdx.x * blockDim.x + threadIdx.x) >> 5;
    int lane = threadIdx.x & 31;
    if (gw >= N_NODES) return;
    const float* a = g_out1 + (size_t)gw * (HEADS * HID);
    float acc[OUTC];
#pragma unroll
    for (int j = 0; j < OUTC; j++) acc[j] = 0.f;
    for (int k = lane; k < HEADS * HID; k += 32) {
        float av = a[k];
#pragma unroll
        for (int j = 0; j < OUTC; j++) acc[j] += av * W2[k * OUTC + j];
    }
#pragma unroll
    for (int j = 0; j < OUTC; j++)
        for (int o = 16; o; o >>= 1)
            acc[j] += __shfl_xor_sync(0xffffffffu, acc[j], o);
    if (lane == 0) {
#pragma unroll
        for (int j = 0; j < OUTC; j++) g_h2[gw * OUTC + j] = acc[j];
    }
}

__global__ void k_e2(const float* __restrict__ a_src2, const float* __restrict__ a_dst2)
{
    int n = blockIdx.x * blockDim.x + threadIdx.x;
    if (n >= N_NODES) return;
    float s = 0.f, d = 0.f;
#pragma unroll
    for (int j = 0; j < OUTC; j++) {
        float h = g_h2[n * OUTC + j];
        s += h * a_src2[j];
        d += h * a_dst2[j];
    }
    g_es2[n] = s; g_ed2[n] = d;
}

// ---------------- GAT layer 2 aggregate (warp per node) ----------------
__global__ void k_agg2(const float* __restrict__ b2)
{
    int gw = (blockIdx.x * blockDim.x + threadIdx.x) >> 5;
    int lane = threadIdx.x & 31;
    if (gw >= N_NODES) return;
    const int n = gw;
    const int beg = g_off[n];
    const int deg = g_off[n + 1] - beg;
    const int tot = deg + 1;
    float edn = g_ed2[n];
    float mx = -FLT_MAX;
    for (int t = lane; t < tot; t += 32) {
        int s = (t < deg) ? g_csrc[beg + t] : n;
        mx = fmaxf(mx, lrelu(g_es2[s] + edn));
    }
    for (int o = 16; o; o >>= 1) mx = fmaxf(mx, __shfl_xor_sync(0xffffffffu, mx, o));
    float sm = 0.f;
    for (int t = lane; t < tot; t += 32) {
        int s = (t < deg) ? g_csrc[beg + t] : n;
        sm += expf(lrelu(g_es2[s] + edn) - mx);
    }
    for (int o = 16; o; o >>= 1) sm += __shfl_xor_sync(0xffffffffu, sm, o);
    float inv = 1.f / (sm + 1e-16f);
    float acc = 0.f;
    for (int base = 0; base < tot; base += 32) {
        int t = base + lane;
        float al = 0.f; int ms = n;
        if (t < tot) {
            int s = (t < deg) ? g_csrc[beg + t] : n;
            ms = s;
            al = expf(lrelu(g_es2[s] + edn) - mx) * inv;
        }
        int nn = min(32, tot - base);
        for (int j = 0; j < nn; j++) {
            float a = __shfl_sync(0xffffffffu, al, j);
            int s = __shfl_sync(0xffffffffu, ms, j);
            if (lane < OUTC) acc += g_h2[s * OUTC + lane] * a;
        }
    }
    if (lane < OUTC) g_emb[n * OUTC + lane] = acc + b2[lane];
}

// ---------------- pair scoring ----------------
__global__ void k_score(const int* __restrict__ pair, float* __restrict__ out)
{
    int p = blockIdx.x * blockDim.x + threadIdx.x;
    if (p >= N_SCORE) return;
    int i = pair[2 * p], j = pair[2 * p + 1];
    const float* a = g_emb + (size_t)i * OUTC;
    const float* b = g_emb + (size_t)j * OUTC;
    float s = 0.f;
#pragma unroll
    for (int c = 0; c < OUTC; c++) s += a[c] * b[c];
    out[p] = s;
}

// ---------------- host ----------------
static inline dim3 gemm_grid(int M, int N, int z = 1)
{ return dim3((N + 127) / 128, (M + 127) / 128, z); }

extern "C" void kernel_launch(void* const* d_in, const int* in_sizes, int n_in,
                              void* d_out, int out_size)
{
    const float* feature_sub = (const float*)d_in[0];
    const float* feature_com = (const float*)d_in[1];
    const float* x           = (const float*)d_in[2];
    const int*   com_idx     = (const int*)d_in[3];
    const int*   edge_index  = (const int*)d_in[4];
    const int*   pair_idx    = (const int*)d_in[5];
    const float* Wq = (const float*)d_in[6];   const float* bq = (const float*)d_in[7];
    const float* Wk = (const float*)d_in[8];   const float* bk = (const float*)d_in[9];
    const float* Wv = (const float*)d_in[10];  const float* bv = (const float*)d_in[11];
    const float* Wf = (const float*)d_in[12];  const float* bf = (const float*)d_in[13];
    const float* W1 = (const float*)d_in[14];
    const float* a_src1 = (const float*)d_in[15];
    const float* a_dst1 = (const float*)d_in[16];
    const float* b1 = (const float*)d_in[17];
    const float* W2 = (const float*)d_in[18];
    const float* a_src2 = (const float*)d_in[19];
    const float* a_dst2 = (const float*)d_in[20];
    const float* b2 = (const float*)d_in[21];
    float* out = (float*)d_out;

    const int* esrc = edge_index;
    const int* edst = edge_index + N_EDGES;

    float *pq, *pk, *pS, *pattn, *pfused, *px, *ph1;
    cudaGetSymbolAddress((void**)&pq,    g_q);
    cudaGetSymbolAddress((void**)&pk,    g_k);
    cudaGetSymbolAddress((void**)&pS,    g_S);
    cudaGetSymbolAddress((void**)&pattn, g_attn);
    cudaGetSymbolAddress((void**)&pfused,g_fused);
    cudaGetSymbolAddress((void**)&px,    g_x);
    cudaGetSymbolAddress((void**)&ph1,   g_h1);

    // --- CSR build ---
    k_reset<<<(N_NODES + 255) / 256, 256>>>();
    k_count<<<(N_EDGES + 255) / 256, 256>>>(edst);
    k_scan<<<1, 1024>>>();
    k_fill<<<(N_EDGES + 255) / 256, 256>>>(esrc, edst);

    // --- cross-attention (tf32 tensor cores) ---
    tgemm_qkv<<<gemm_grid(N_PAIRS, FEAT, 3), 256>>>(
        feature_sub, feature_com, Wq, bq, Wk, bk, Wv, bv);
    tgemm<true><<<gemm_grid(N_PAIRS, N_PAIRS), 256>>>(
        pq, pk, pS, N_PAIRS, N_PAIRS, FEAT, 1.f / sqrtf((float)FEAT), nullptr, nullptr);
    k_softmax<<<N_PAIRS, 256>>>();
    tgemm_sv_part<<<gemm_grid(N_PAIRS, FEAT, SPLITK), 256>>>();
    k_combine_sv<<<(SV_SZ + 255) / 256, 256>>>(feature_sub);
    tgemm<false><<<gemm_grid(N_PAIRS, FEAT), 256>>>(
        pattn, Wf, pfused, N_PAIRS, FEAT, FEAT, 1.f, bf, nullptr);

    // --- write fused features into node feature copy (last-index-wins) ---
    k_copyx<<<((N_NODES * FEAT / 4) + 255) / 256, 256>>>(x);
    k_winner<<<(N_PAIRS + 255) / 256, 256>>>(com_idx);
    k_scatter<<<N_PAIRS, 128>>>(com_idx);

    // --- GAT layer 1 ---
    tgemm<false><<<gemm_grid(N_NODES, HEADS * HID), 256>>>(
        px, W1, ph1, N_NODES, HEADS * HID, FEAT, 1.f, nullptr, nullptr);
    k_e1<<<(N_NODES * 32 + 255) / 256, 256>>>(a_src1, a_dst1);
    k_agg1<<<N_NODES, 128>>>(b1);

    // --- GAT layer 2 ---
    k_h2<<<(N_NODES * 32 + 255) / 256, 256>>>(W2);
    k_e2<<<(N_NODES + 255) / 256, 256>>>(a_src2, a_dst2);
    k_agg2<<<(N_NODES * 32 + 255) / 256, 256>>>(b2);

    // --- pair scores ---
    k_score<<<(N_SCORE + 255) / 256, 256>>>(pair_idx, out);
}

// round 16
// speedup vs baseline: 1.1368x; 1.1344x over previous
#include <cuda_runtime.h>
#include <cfloat>
#include <math.h>
#include <stdint.h>

#define N_NODES 50000
#define N_PAIRS 4096
#define N_EDGES 500000
#define N_SCORE 1000000
#define FEAT 300
#define HID 128
#define HEADS 3
#define OUTC 10
#define SPLITK 3
#define SV_SZ (N_PAIRS * FEAT)
// split-K chunk: multiple of 4 (16B-aligned float4 K-loads), even (half2 K-pairing)
#define SV_CHUNK 1368

// ---------------- scratch (device globals; no runtime allocation) ----------------
__device__ float g_q[N_PAIRS * FEAT];
__device__ float g_k[N_PAIRS * FEAT];
__device__ float g_v[N_PAIRS * FEAT];
__device__ float g_S[(size_t)N_PAIRS * N_PAIRS];          // 64 MB
__device__ float g_attn[N_PAIRS * FEAT];
__device__ float g_fused[N_PAIRS * FEAT];
__device__ float g_part[(size_t)SPLITK * SV_SZ];          // split-K partials
__device__ float g_x[(size_t)N_NODES * FEAT];             // 60 MB
__device__ float g_h1[(size_t)N_NODES * HEADS * HID];     // 76.8 MB
__device__ float g_out1[(size_t)N_NODES * HEADS * HID];   // 76.8 MB
__device__ float g_es1[N_NODES * HEADS];
__device__ float g_ed1[N_NODES * HEADS];
__device__ float g_h2[N_NODES * OUTC];
__device__ float g_emb[N_NODES * OUTC];
__device__ float g_es2[N_NODES];
__device__ float g_ed2[N_NODES];
__device__ int   g_cnt[N_NODES];
__device__ int   g_off[N_NODES + 1];
__device__ int   g_cur[N_NODES];
__device__ int   g_csrc[N_EDGES];
__device__ int   g_win[N_NODES];

// ---------------- helpers ----------------
__device__ __forceinline__ float4 ld4k(const float* __restrict__ p, int k, int kEnd)
{
    if (k + 3 < kEnd) return *(const float4*)(p + k);
    float4 v = make_float4(0.f, 0.f, 0.f, 0.f);
    if (k + 0 < kEnd) v.x = p[k + 0];
    if (k + 1 < kEnd) v.y = p[k + 1];
    if (k + 2 < kEnd) v.z = p[k + 2];
    if (k + 3 < kEnd) v.w = p[k + 3];
    return v;
}

// pack two f32 into half2 bits: low 16 bits = lo (smaller k index)
__device__ __forceinline__ uint32_t f2h2(float lo, float hi)
{
    uint32_t u;
    asm("cvt.rn.f16x2.f32 %0, %1, %2;" : "=r"(u) : "f"(hi), "f"(lo));
    return u;
}

__device__ __forceinline__ void mma_f16(float* c, const uint32_t* a, const uint32_t* b)
{
    asm volatile(
        "mma.sync.aligned.m16n8k16.row.col.f32.f16.f16.f32 "
        "{%0,%1,%2,%3}, {%4,%5,%6,%7}, {%8,%9}, {%0,%1,%2,%3};"
        : "+f"(c[0]), "+f"(c[1]), "+f"(c[2]), "+f"(c[3])
        : "r"(a[0]), "r"(a[1]), "r"(a[2]), "r"(a[3]),
          "r"(b[0]), "r"(b[1]));
}

// ---------------- fp16 tensor-core GEMM: 128x128x16 tile, 8 warps, m16n8k16 ----------------
// Inputs converted f32->f16 at smem commit (11-bit significand, same as tf32).
// smem packed half2 along K: As2[k/2][m], Bs2[k/2][n]. Double-buffered.
// A: [M,K] row-major. B: [K,N] row-major (TB=false) or [N,K] row-major (TB=true).
// PARTIAL: raw partial result to C. kBegin must be a multiple of 4.
template <bool TB, bool PARTIAL>
__device__ __forceinline__ void f16_body(
    const float* __restrict__ A, const float* __restrict__ B,
    float* __restrict__ C, int M, int N, int K,
    int kBegin, int kEnd, float alpha,
    const float* __restrict__ bias, const float* __restrict__ addm, int ldc)
{
    constexpr int BM = 128, BN = 128, BK = 16, LDSM = 136;
    __shared__ uint32_t As2[2][BK / 2][LDSM];   // [buf][k2][m]
    __shared__ uint32_t Bs2[2][BK / 2][LDSM];   // [buf][k2][n]

    const int tid  = threadIdx.x;       // 256
    const int row0 = blockIdx.y * BM;
    const int col0 = blockIdx.x * BN;
    const int lane = tid & 31;
    const int wid  = tid >> 5;
    const int wm   = wid >> 2;          // 0..1 -> 64 rows each
    const int wn   = wid & 3;           // 0..3 -> 32 cols each
    const int lr   = lane >> 2;         // 0..7
    const int lc   = lane & 3;          // 0..3
    // loaders: A (and B when TB): one float4 along K per thread, h=0/1 for k+8
    const int lrow = tid >> 1;          // 0..127
    const int lkq  = (tid & 1) * 4;     // 0 or 4
    // B non-T loader: thread owns k2 = bkk2 (rows 2*bkk2, 2*bkk2+1), 4 cols
    const int bkk2 = tid >> 5;          // 0..7
    const int bnq  = (tid & 31) * 4;    // 0..124

    float acc[4][4][4];
#pragma unroll
    for (int i = 0; i < 4; i++)
#pragma unroll
        for (int j = 0; j < 4; j++)
#pragma unroll
            for (int t = 0; t < 4; t++) acc[i][j][t] = 0.f;

    const int ga_row  = row0 + lrow;
    const int gb_colT = col0 + lrow;

    float4 pa[2], pb[2];

    auto fetch = [&](int k0) {
        if (TB) {
#pragma unroll
            for (int h = 0; h < 2; h++) {
                int kk = k0 + lkq + h * 8;
                pa[h] = (ga_row < M) ? ld4k(A + (size_t)ga_row * K, kk, kEnd)
                                     : make_float4(0.f, 0.f, 0.f, 0.f);
                pb[h] = (gb_colT < N) ? ld4k(B + (size_t)gb_colT * K, kk, kEnd)
                                      : make_float4(0.f, 0.f, 0.f, 0.f);
            }
        } else {
#pragma unroll
            for (int h = 0; h < 2; h++) {
                int kk = k0 + lkq + h * 8;
                pa[h] = (ga_row < M) ? ld4k(A + (size_t)ga_row * K, kk, kEnd)
                                     : make_float4(0.f, 0.f, 0.f, 0.f);
            }
            // B rows 2*bkk2 and 2*bkk2+1, cols bnq..bnq+3
#pragma unroll
            for (int h = 0; h < 2; h++) {
                int gk = k0 + 2 * bkk2 + h;
                pb[h] = make_float4(0.f, 0.f, 0.f, 0.f);
                if (gk < kEnd) {
                    const float* p = B + (size_t)gk * N;
                    int gc = col0 + bnq;
                    if (gc + 3 < N) pb[h] = *(const float4*)(p + gc);
                    else {
                        if (gc + 0 < N) pb[h].x = p[gc + 0];
                        if (gc + 1 < N) pb[h].y = p[gc + 1];
                        if (gc + 2 < N) pb[h].z = p[gc + 2];
                        if (gc + 3 < N) pb[h].w = p[gc + 3];
                    }
                }
            }
        }
    };

    auto commit = [&](int buf) {
#pragma unroll
        for (int h = 0; h < 2; h++) {
            // A: k-quad (lkq+h*8 .. +3) -> k2 = lkq/2 + h*4 (+0, +1)
            const int k2a = (lkq >> 1) + h * 4;
            As2[buf][k2a + 0][lrow] = f2h2(pa[h].x, pa[h].y);
            As2[buf][k2a + 1][lrow] = f2h2(pa[h].z, pa[h].w);
        }
        if (TB) {
#pragma unroll
            for (int h = 0; h < 2; h++) {
                const int k2b = (lkq >> 1) + h * 4;
                Bs2[buf][k2b + 0][lrow] = f2h2(pb[h].x, pb[h].y);
                Bs2[buf][k2b + 1][lrow] = f2h2(pb[h].z, pb[h].w);
            }
        } else {
            // pair across the two K rows, same n
            uint4 t;
            t.x = f2h2(pb[0].x, pb[1].x);
            t.y = f2h2(pb[0].y, pb[1].y);
            t.z = f2h2(pb[0].z, pb[1].z);
            t.w = f2h2(pb[0].w, pb[1].w);
            *(uint4*)&Bs2[buf][bkk2][bnq] = t;
        }
    };

    // prologue: stage 0
    fetch(kBegin);
    commit(0);
    __syncthreads();

    int cur = 0;
    for (int k0 = kBegin; k0 < kEnd; k0 += BK) {
        const bool has_next = (k0 + BK < kEnd);
        if (has_next) fetch(k0 + BK);

        // fragments + 16 MMAs on current stage
        uint32_t af[4][4], bf[4][2];
#pragma unroll
        for (int mt = 0; mt < 4; mt++) {
            int m0 = wm * 64 + mt * 16;
            af[mt][0] = As2[cur][lc][m0 + lr];
            af[mt][1] = As2[cur][lc][m0 + lr + 8];
            af[mt][2] = As2[cur][lc + 4][m0 + lr];
            af[mt][3] = As2[cur][lc + 4][m0 + lr + 8];
        }
#pragma unroll
        for (int nt = 0; nt < 4; nt++) {
            int n0 = wn * 32 + nt * 8;
            bf[nt][0] = Bs2[cur][lc][n0 + lr];
            bf[nt][1] = Bs2[cur][lc + 4][n0 + lr];
        }
#pragma unroll
        for (int mt = 0; mt < 4; mt++)
#pragma unroll
            for (int nt = 0; nt < 4; nt++)
                mma_f16(acc[mt][nt], af[mt], bf[nt]);

        if (has_next) {
            commit(cur ^ 1);
            __syncthreads();
        }
        cur ^= 1;
    }

    // epilogue (f32 accumulator layout identical to m16n8k8)
#pragma unroll
    for (int mt = 0; mt < 4; mt++) {
#pragma unroll
        for (int nt = 0; nt < 4; nt++) {
#pragma unroll
            for (int half = 0; half < 2; half++) {
                int r = row0 + wm * 64 + mt * 16 + lr + half * 8;
                int c = col0 + wn * 32 + nt * 8 + 2 * lc;
                if (r >= M) continue;
                float v0 = acc[mt][nt][half * 2 + 0];
                float v1 = acc[mt][nt][half * 2 + 1];
                if (!PARTIAL) {
                    v0 *= alpha; v1 *= alpha;
                    if (bias) { v0 += bias[c]; if (c + 1 < N) v1 += bias[c + 1]; }
                    if (addm) {
                        v0 += addm[(size_t)r * N + c];
                        if (c + 1 < N) v1 += addm[(size_t)r * N + c + 1];
                    }
                }
                float* dst = C + (size_t)r * ldc + c;
                if (c + 1 < N) *(float2*)dst = make_float2(v0, v1);
                else if (c < N) *dst = v0;
            }
        }
    }
}

template <bool TB>
__global__ void __launch_bounds__(256, 2) tgemm(
    const float* __restrict__ A, const float* __restrict__ B,
    float* __restrict__ C, int M, int N, int K, float alpha,
    const float* __restrict__ bias, const float* __restrict__ addm)
{
    f16_body<TB, false>(A, B, C, M, N, K, 0, K, alpha, bias, addm, N);
}

// batched q/k/v projection: blockIdx.z selects (A, W, b, C)
__global__ void __launch_bounds__(256, 2) tgemm_qkv(
    const float* __restrict__ fsub, const float* __restrict__ fcom,
    const float* __restrict__ Wq, const float* __restrict__ bq,
    const float* __restrict__ Wk, const float* __restrict__ bk,
    const float* __restrict__ Wv, const float* __restrict__ bv)
{
    const float* A; const float* W; const float* b; float* C;
    if (blockIdx.z == 0)      { A = fsub; W = Wq; b = bq; C = g_q; }
    else if (blockIdx.z == 1) { A = fcom; W = Wk; b = bk; C = g_k; }
    else                      { A = fcom; W = Wv; b = bv; C = g_v; }
    f16_body<false, false>(A, W, C, N_PAIRS, FEAT, FEAT, 0, FEAT, 1.f, b, nullptr, FEAT);
}

// split-K S@v partials: blockIdx.z = split id
__global__ void __launch_bounds__(256, 2) tgemm_sv_part()
{
    const int z = blockIdx.z;
    const int kb = z * SV_CHUNK;
    const int ke = min(N_PAIRS, kb + SV_CHUNK);
    f16_body<false, true>(g_S, g_v, g_part + (size_t)z * SV_SZ,
                          N_PAIRS, FEAT, N_PAIRS, kb, ke, 1.f, nullptr, nullptr, FEAT);
}

__global__ void k_combine_sv(const float* __restrict__ fsub)
{
    int i = blockIdx.x * blockDim.x + threadIdx.x;
    if (i < SV_SZ)
        g_attn[i] = g_part[i] + g_part[i + SV_SZ] + g_part[i + 2 * SV_SZ] + fsub[i];
}

// ---------------- row softmax on g_S (4096 rows of 4096) ----------------
__global__ void k_softmax()
{
    int row = blockIdx.x;
    float* p = g_S + (size_t)row * N_PAIRS;
    int tid = threadIdx.x;               // 256
    float v[16];
    float mx = -FLT_MAX;
#pragma unroll
    for (int i = 0; i < 16; i++) { v[i] = p[tid + i * 256]; mx = fmaxf(mx, v[i]); }
    __shared__ float red[256];
    red[tid] = mx; __syncthreads();
    for (int s = 128; s > 0; s >>= 1) {
        if (tid < s) red[tid] = fmaxf(red[tid], red[tid + s]);
        __syncthreads();
    }
    mx = red[0]; __syncthreads();
    float sum = 0.f;
#pragma unroll
    for (int i = 0; i < 16; i++) { v[i] = expf(v[i] - mx); sum += v[i]; }
    red[tid] = sum; __syncthreads();
    for (int s = 128; s > 0; s >>= 1) {
        if (tid < s) red[tid] += red[tid + s];
        __syncthreads();
    }
    float inv = 1.f / red[0];
#pragma unroll
    for (int i = 0; i < 16; i++) p[tid + i * 256] = v[i] * inv;
}

// ---------------- CSR build ----------------
__global__ void k_reset()
{
    int i = blockIdx.x * blockDim.x + threadIdx.x;
    if (i < N_NODES) { g_cnt[i] = 0; g_win[i] = -1; }
}

__global__ void k_count(const int* __restrict__ dst)
{
    int e = blockIdx.x * blockDim.x + threadIdx.x;
    if (e < N_EDGES) atomicAdd(&g_cnt[dst[e]], 1);
}

__global__ void k_scan()
{
    __shared__ int sh[1024];
    __shared__ int carry;
    int tid = threadIdx.x;
    if (tid == 0) { carry = 0; g_off[0] = 0; }
    __syncthreads();
    for (int base = 0; base < N_NODES; base += 1024) {
        int i = base + tid;
        int v = (i < N_NODES) ? g_cnt[i] : 0;
        sh[tid] = v;
        __syncthreads();
        for (int o = 1; o < 1024; o <<= 1) {
            int t = (tid >= o) ? sh[tid - o] : 0;
            __syncthreads();
            sh[tid] += t;
            __syncthreads();
        }
        int c = carry;
        if (i < N_NODES) { g_off[i + 1] = c + sh[tid]; g_cur[i] = c + sh[tid] - v; }
        __syncthreads();
        if (tid == 0) carry += sh[1023];
        __syncthreads();
    }
}

__global__ void k_fill(const int* __restrict__ src, const int* __restrict__ dst)
{
    int e = blockIdx.x * blockDim.x + threadIdx.x;
    if (e < N_EDGES) {
        int d = dst[e];
        int pos = atomicAdd(&g_cur[d], 1);
        g_csrc[pos] = src[e];
    }
}

// ---------------- feature scatter (last index wins) ----------------
__global__ void k_copyx(const float* __restrict__ x)
{
    int i = blockIdx.x * blockDim.x + threadIdx.x;
    const int n4 = (N_NODES * FEAT) / 4;
    if (i < n4) ((float4*)g_x)[i] = ((const float4*)x)[i];
}

__global__ void k_winner(const int* __restrict__ com_idx)
{
    int i = blockIdx.x * blockDim.x + threadIdx.x;
    if (i < N_PAIRS) atomicMax(&g_win[com_idx[i]], i);
}

__global__ void k_scatter(const int* __restrict__ com_idx)
{
    int i = blockIdx.x;
    int node = com_idx[i];
    if (g_win[node] != i) return;
    for (int c = threadIdx.x; c < FEAT; c += blockDim.x)
        g_x[(size_t)node * FEAT + c] = g_fused[(size_t)i * FEAT + c];
}

// ---------------- GAT layer 1: per-node attention coefficients ----------------
__global__ void k_e1(const float* __restrict__ a_src1, const float* __restrict__ a_dst1)
{
    int gw = (blockIdx.x * blockDim.x + threadIdx.x) >> 5;
    int lane = threadIdx.x & 31;
    if (gw >= N_NODES) return;
    const float* hp = g_h1 + (size_t)gw * (HEADS * HID);
#pragma unroll
    for (int h = 0; h < HEADS; h++) {
        float ps = 0.f, pd = 0.f;
#pragma unroll
        for (int t = 0; t < 4; t++) {
            int c = h * HID + lane + t * 32;
            float hv = hp[c];
            ps += hv * a_src1[c];
            pd += hv * a_dst1[c];
        }
        for (int o = 16; o; o >>= 1) {
            ps += __shfl_xor_sync(0xffffffffu, ps, o);
            pd += __shfl_xor_sync(0xffffffffu, pd, o);
        }
        if (lane == 0) { g_es1[gw * 3 + h] = ps; g_ed1[gw * 3 + h] = pd; }
    }
}

__device__ __forceinline__ float lrelu(float x) { return x > 0.f ? x : 0.2f * x; }

// ---------------- GAT layer 1: softmax-aggregate per dst node, fused ELU ----------------
__global__ void k_agg1(const float* __restrict__ b1)
{
    __shared__ float shred[3][128];
    __shared__ float shal[64][3];
    __shared__ int   shsrc[64];
    const int n = blockIdx.x;
    const int tid = threadIdx.x;          // 128
    const int beg = g_off[n];
    const int deg = g_off[n + 1] - beg;
    const int tot = deg + 1;              // + self loop
    float edn[3];
#pragma unroll
    for (int h = 0; h < 3; h++) edn[h] = g_ed1[n * 3 + h];

    float mx[3] = { -FLT_MAX, -FLT_MAX, -FLT_MAX };
    for (int t = tid; t < tot; t += 128) {
        int s = (t < deg) ? g_csrc[beg + t] : n;
#pragma unroll
        for (int h = 0; h < 3; h++) {
            float e = lrelu(g_es1[s * 3 + h] + edn[h]);
            mx[h] = fmaxf(mx[h], e);
        }
    }
#pragma unroll
    for (int h = 0; h < 3; h++) shred[h][tid] = mx[h];
    __syncthreads();
    for (int s = 64; s > 0; s >>= 1) {
        if (tid < s) {
#pragma unroll
            for (int h = 0; h < 3; h++)
                shred[h][tid] = fmaxf(shred[h][tid], shred[h][tid + s]);
        }
        __syncthreads();
    }
#pragma unroll
    for (int h = 0; h < 3; h++) mx[h] = shred[h][0];
    __syncthreads();

    float sm[3] = { 0.f, 0.f, 0.f };
    for (int t = tid; t < tot; t += 128) {
        int s = (t < deg) ? g_csrc[beg + t] : n;
#pragma unroll
        for (int h = 0; h < 3; h++) {
            float e = lrelu(g_es1[s * 3 + h] + edn[h]);
            sm[h] += expf(e - mx[h]);
        }
    }
#pragma unroll
    for (int h = 0; h < 3; h++) shred[h][tid] = sm[h];
    __syncthreads();
    for (int s = 64; s > 0; s >>= 1) {
        if (tid < s) {
#pragma unroll
            for (int h = 0; h < 3; h++)
                shred[h][tid] += shred[h][tid + s];
        }
        __syncthreads();
    }
    float inv[3];
#pragma unroll
    for (int h = 0; h < 3; h++) inv[h] = 1.f / (shred[h][0] + 1e-16f);
    __syncthreads();

    float acc[3] = { 0.f, 0.f, 0.f };
    for (int base = 0; base < tot; base += 64) {
        int nn = min(64, tot - base);
        if (tid < nn) {
            int t = base + tid;
            int s = (t < deg) ? g_csrc[beg + t] : n;
            shsrc[tid] = s;
#pragma unroll
            for (int h = 0; h < 3; h++) {
                float e = lrelu(g_es1[s * 3 + h] + edn[h]);
                shal[tid][h] = expf(e - mx[h]) * inv[h];
            }
        }
        __syncthreads();
        for (int j = 0; j < nn; j++) {
            const float* hp = g_h1 + (size_t)shsrc[j] * (HEADS * HID);
            float a0 = shal[j][0], a1 = shal[j][1], a2 = shal[j][2];
            acc[0] += hp[tid] * a0;
            acc[1] += hp[128 + tid] * a1;
            acc[2] += hp[256 + tid] * a2;
        }
        __syncthreads();
    }
#pragma unroll
    for (int h = 0; h < 3; h++) {
        float v = acc[h] + b1[h * HID + tid];
        g_out1[(size_t)n * (HEADS * HID) + h * HID + tid] = v > 0.f ? v : expm1f(v);
    }
}

// ---------------- GAT layer 2: h2 = out1 @ W2, fused e2 coefficients ----------------
__global__ void k_h2(const float* __restrict__ W2,
                     const float* __restrict__ a_src2, const float* __restrict__ a_dst2)
{
    int gw = (blockIdx.x * blockDim.x + threadIdx.x) >> 5;
    int lane = threadIdx.x & 31;
    if (gw >= N_NODES) return;
    const float* a = g_out1 + (size_t)gw * (HEADS * HID);
    float acc[OUTC];
#pragma unroll
    for (int j = 0; j < OUTC; j++) acc[j] = 0.f;
    for (int k = lane; k < HEADS * HID; k += 32) {
        float av = a[k];
#pragma unroll
        for (int j = 0; j < OUTC; j++) acc[j] += av * W2[k * OUTC + j];
    }
#pragma unroll
    for (int j = 0; j < OUTC; j++)
        for (int o = 16; o; o >>= 1)
            acc[j] += __shfl_xor_sync(0xffffffffu, acc[j], o);
    if (lane == 0) {
        float s = 0.f, d = 0.f;
#pragma unroll
        for (int j = 0; j < OUTC; j++) {
            g_h2[gw * OUTC + j] = acc[j];
            s += acc[j] * a_src2[j];
            d += acc[j] * a_dst2[j];
        }
        g_es2[gw] = s; g_ed2[gw] = d;
    }
}

// ---------------- GAT layer 2 aggregate (warp per node) ----------------
__global__ void k_agg2(const float* __restrict__ b2)
{
    int gw = (blockIdx.x * blockDim.x + threadIdx.x) >> 5;
    int lane = threadIdx.x & 31;
    if (gw >= N_NODES) return;
    const int n = gw;
    const int beg = g_off[n];
    const int deg = g_off[n + 1] - beg;
    const int tot = deg + 1;
    float edn = g_ed2[n];
    float mx = -FLT_MAX;
    for (int t = lane; t < tot; t += 32) {
        int s = (t < deg) ? g_csrc[beg + t] : n;
        mx = fmaxf(mx, lrelu(g_es2[s] + edn));
    }
    for (int o = 16; o; o >>= 1) mx = fmaxf(mx, __shfl_xor_sync(0xffffffffu, mx, o));
    float sm = 0.f;
    for (int t = lane; t < tot; t += 32) {
        int s = (t < deg) ? g_csrc[beg + t] : n;
        sm += expf(lrelu(g_es2[s] + edn) - mx);
    }
    for (int o = 16; o; o >>= 1) sm += __shfl_xor_sync(0xffffffffu, sm, o);
    float inv = 1.f / (sm + 1e-16f);
    float acc = 0.f;
    for (int base = 0; base < tot; base += 32) {
        int t = base + lane;
        float al = 0.f; int ms = n;
        if (t < tot) {
            int s = (t < deg) ? g_csrc[beg + t] : n;
            ms = s;
            al = expf(lrelu(g_es2[s] + edn) - mx) * inv;
        }
        int nn = min(32, tot - base);
        for (int j = 0; j < nn; j++) {
            float a = __shfl_sync(0xffffffffu, al, j);
            int s = __shfl_sync(0xffffffffu, ms, j);
            if (lane < OUTC) acc += g_h2[s * OUTC + lane] * a;
        }
    }
    if (lane < OUTC) g_emb[n * OUTC + lane] = acc + b2[lane];
}

// ---------------- pair scoring ----------------
__global__ void k_score(const int* __restrict__ pair, float* __restrict__ out)
{
    int p = blockIdx.x * blockDim.x + threadIdx.x;
    if (p >= N_SCORE) return;
    int i = pair[2 * p], j = pair[2 * p + 1];
    const float* a = g_emb + (size_t)i * OUTC;
    const float* b = g_emb + (size_t)j * OUTC;
    float s = 0.f;
#pragma unroll
    for (int c = 0; c < OUTC; c++) s += a[c] * b[c];
    out[p] = s;
}

// ---------------- host ----------------
static inline dim3 gemm_grid(int M, int N, int z = 1)
{ return dim3((N + 127) / 128, (M + 127) / 128, z); }

extern "C" void kernel_launch(void* const* d_in, const int* in_sizes, int n_in,
                              void* d_out, int out_size)
{
    const float* feature_sub = (const float*)d_in[0];
    const float* feature_com = (const float*)d_in[1];
    const float* x           = (const float*)d_in[2];
    const int*   com_idx     = (const int*)d_in[3];
    const int*   edge_index  = (const int*)d_in[4];
    const int*   pair_idx    = (const int*)d_in[5];
    const float* Wq = (const float*)d_in[6];   const float* bq = (const float*)d_in[7];
    const float* Wk = (const float*)d_in[8];   const float* bk = (const float*)d_in[9];
    const float* Wv = (const float*)d_in[10];  const float* bv = (const float*)d_in[11];
    const float* Wf = (const float*)d_in[12];  const float* bf = (const float*)d_in[13];
    const float* W1 = (const float*)d_in[14];
    const float* a_src1 = (const float*)d_in[15];
    const float* a_dst1 = (const float*)d_in[16];
    const float* b1 = (const float*)d_in[17];
    const float* W2 = (const float*)d_in[18];
    const float* a_src2 = (const float*)d_in[19];
    const float* a_dst2 = (const float*)d_in[20];
    const float* b2 = (const float*)d_in[21];
    float* out = (float*)d_out;

    const int* esrc = edge_index;
    const int* edst = edge_index + N_EDGES;

    float *pq, *pk, *pS, *pattn, *pfused, *px, *ph1;
    cudaGetSymbolAddress((void**)&pq,    g_q);
    cudaGetSymbolAddress((void**)&pk,    g_k);
    cudaGetSymbolAddress((void**)&pS,    g_S);
    cudaGetSymbolAddress((void**)&pattn, g_attn);
    cudaGetSymbolAddress((void**)&pfused,g_fused);
    cudaGetSymbolAddress((void**)&px,    g_x);
    cudaGetSymbolAddress((void**)&ph1,   g_h1);

    // --- CSR build ---
    k_reset<<<(N_NODES + 255) / 256, 256>>>();
    k_count<<<(N_EDGES + 255) / 256, 256>>>(edst);
    k_scan<<<1, 1024>>>();
    k_fill<<<(N_EDGES + 255) / 256, 256>>>(esrc, edst);

    // --- cross-attention (fp16 tensor cores, fp32 accumulate) ---
    tgemm_qkv<<<gemm_grid(N_PAIRS, FEAT, 3), 256>>>(
        feature_sub, feature_com, Wq, bq, Wk, bk, Wv, bv);
    tgemm<true><<<gemm_grid(N_PAIRS, N_PAIRS), 256>>>(
        pq, pk, pS, N_PAIRS, N_PAIRS, FEAT, 1.f / sqrtf((float)FEAT), nullptr, nullptr);
    k_softmax<<<N_PAIRS, 256>>>();
    tgemm_sv_part<<<gemm_grid(N_PAIRS, FEAT, SPLITK), 256>>>();
    k_combine_sv<<<(SV_SZ + 255) / 256, 256>>>(feature_sub);
    tgemm<false><<<gemm_grid(N_PAIRS, FEAT), 256>>>(
        pattn, Wf, pfused, N_PAIRS, FEAT, FEAT, 1.f, bf, nullptr);

    // --- write fused features into node feature copy (last-index-wins) ---
    k_copyx<<<((N_NODES * FEAT / 4) + 255) / 256, 256>>>(x);
    k_winner<<<(N_PAIRS + 255) / 256, 256>>>(com_idx);
    k_scatter<<<N_PAIRS, 128>>>(com_idx);

    // --- GAT layer 1 ---
    tgemm<false><<<gemm_grid(N_NODES, HEADS * HID), 256>>>(
        px, W1, ph1, N_NODES, HEADS * HID, FEAT, 1.f, nullptr, nullptr);
    k_e1<<<(N_NODES * 32 + 255) / 256, 256>>>(a_src1, a_dst1);
    k_agg1<<<N_NODES, 128>>>(b1);

    // --- GAT layer 2 (e2 fused into h2) ---
    k_h2<<<(N_NODES * 32 + 255) / 256, 256>>>(W2, a_src2, a_dst2);
    k_agg2<<<(N_NODES * 32 + 255) / 256, 256>>>(b2);

    // --- pair scores ---
    k_score<<<(N_SCORE + 255) / 256, 256>>>(pair_idx, out);
}